// round 1
// baseline (speedup 1.0000x reference)
#include <cuda_runtime.h>
#include <cuda_bf16.h>

#define NN 8192
#define IN_F 256
#define OUT_F 64
#define LEAK 0.2f

// ---------------- scratch (device globals; no runtime allocation) ----------
__device__ float g_h[NN * OUT_F];
__device__ float g_si[NN];
__device__ float g_sj[NN];
__device__ float g_gamma[NN];
__device__ float g_beta[NN];

// ---------------- packed f32x2 helpers (sm_100+) ---------------------------
typedef unsigned long long ull;

__device__ __forceinline__ void ffma2(ull& d, ull a, ull b) {
    asm("fma.rn.f32x2 %0, %1, %2, %0;" : "+l"(d) : "l"(a), "l"(b));
}
__device__ __forceinline__ ull pack2(float x) {
    ull r;
    asm("mov.b64 %0, {%1, %1};" : "=l"(r) : "f"(x));
    return r;
}

// ============================================================================
// Kernel 1: h = x @ W ; s_i = h@a_i ; s_j = h@a_j ; gamma = h@w_g + 1 ; beta
// 256 blocks x 256 threads, 32 rows/block. W cached in SMEM per block.
// ============================================================================
#define PREP_SMEM ((IN_F * OUT_F + 32 * IN_F + 4 * OUT_F) * 4)

__global__ __launch_bounds__(256, 1) void prep_kernel(
    const float* __restrict__ x, const float* __restrict__ W,
    const float* __restrict__ a_i, const float* __restrict__ a_j,
    const float* __restrict__ w_g, const float* __restrict__ w_b)
{
    extern __shared__ float sm[];
    float* Ws = sm;                          // [256][64]
    float* xs = Ws + IN_F * OUT_F;           // [32][256]
    float* vs = xs + 32 * IN_F;              // 4 x [64]

    const int t = threadIdx.x;
    const int row0 = blockIdx.x * 32;

    for (int i = t; i < IN_F * OUT_F / 4; i += 256)
        ((float4*)Ws)[i] = ((const float4*)W)[i];
    for (int i = t; i < 32 * IN_F / 4; i += 256)
        ((float4*)xs)[i] = ((const float4*)(x + (size_t)row0 * IN_F))[i];
    if (t < OUT_F) {
        vs[t]            = a_i[t];
        vs[OUT_F + t]    = a_j[t];
        vs[2*OUT_F + t]  = w_g[t];
        vs[3*OUT_F + t]  = w_b[t];
    }
    __syncthreads();

    const int row = t >> 3;        // 0..31
    const int fg  = t & 7;         // 0..7
    const int f0  = fg * 8;

    float acc[8];
#pragma unroll
    for (int i = 0; i < 8; i++) acc[i] = 0.0f;

    const float* xr = xs + row * IN_F;
#pragma unroll 4
    for (int k = 0; k < IN_F; k++) {
        const float xv = xr[k];
        const float* wr = Ws + k * OUT_F + f0;
#pragma unroll
        for (int ff = 0; ff < 8; ff++) acc[ff] = fmaf(xv, wr[ff], acc[ff]);
    }

    const int grow = row0 + row;
    float4* hp = (float4*)(g_h + (size_t)grow * OUT_F + f0);
    hp[0] = make_float4(acc[0], acc[1], acc[2], acc[3]);
    hp[1] = make_float4(acc[4], acc[5], acc[6], acc[7]);

    float psi = 0.f, psj = 0.f, pg = 0.f, pb = 0.f;
#pragma unroll
    for (int ff = 0; ff < 8; ff++) {
        const float a = acc[ff];
        psi = fmaf(a, vs[f0 + ff], psi);
        psj = fmaf(a, vs[OUT_F + f0 + ff], psj);
        pg  = fmaf(a, vs[2*OUT_F + f0 + ff], pg);
        pb  = fmaf(a, vs[3*OUT_F + f0 + ff], pb);
    }
    // reduce across the 8 fg lanes (contiguous within the warp)
#pragma unroll
    for (int off = 4; off > 0; off >>= 1) {
        psi += __shfl_down_sync(0xffffffffu, psi, off);
        psj += __shfl_down_sync(0xffffffffu, psj, off);
        pg  += __shfl_down_sync(0xffffffffu, pg,  off);
        pb  += __shfl_down_sync(0xffffffffu, pb,  off);
    }
    if (fg == 0) {
        g_si[grow]    = psi;
        g_sj[grow]    = psj;
        g_gamma[grow] = pg + 1.0f;
        g_beta[grow]  = pb;
    }
}

// ============================================================================
// Kernel 2: fused masked softmax-attention + FiLM.
// 128 blocks x 256 threads. Block = 64 rows. j tiled by 128.
// w tile built in SMEM (in-place over the adj tile), P@H on packed f32x2.
// ============================================================================
#define BM 64
#define BN 128
#define BNP 132   // padded stride (floats): conflict-free w reads, 16B aligned

// smem (floats): h_s[BN*OUT_F] | w_s[BM*BNP] | sj_s[BN] | si_s[BM] | denom_s[BM]
#define MAIN_SMEM_FLOATS (BN*OUT_F + BM*BNP + BN + BM + BM)
#define MAIN_SMEM (MAIN_SMEM_FLOATS * 4)

__global__ __launch_bounds__(256, 1) void attn_kernel(
    const int* __restrict__ adj, float* __restrict__ out)
{
    extern __shared__ float sm[];
    float* h_s     = sm;                      // [BN][64]
    float* w_s     = h_s + BN * OUT_F;        // [BM][BNP] (first holds adj ints)
    float* sj_s    = w_s + BM * BNP;          // [BN]
    float* si_s    = sj_s + BN;               // [BM]
    float* denom_s = si_s + BM;               // [BM]
    int*   wi_s    = (int*)w_s;

    const int t  = threadIdx.x;
    const int i0 = blockIdx.x * BM;

    if (t < BM) si_s[t] = g_si[i0 + t];

    const int rg = t >> 3;          // 0..31 -> rows 2rg, 2rg+1
    const int fg = t & 7;           // 0..7  -> f0 = fg*8
    const int r0 = rg * 2, r1 = r0 + 1;
    const int f0 = fg * 8;

    ull a00 = 0, a01 = 0, a02 = 0, a03 = 0;
    ull a10 = 0, a11 = 0, a12 = 0, a13 = 0;
    float d0 = 0.f, d1 = 0.f;

    for (int j0 = 0; j0 < NN; j0 += BN) {
        __syncthreads();   // previous FMA phase done with smem

        // h tile: contiguous 8192 floats
        {
            const float4* src = (const float4*)(g_h + (size_t)j0 * OUT_F);
#pragma unroll
            for (int k = 0; k < 8; k++)
                ((float4*)h_s)[t + k * 256] = src[t + k * 256];
        }
        // sj tile
        if (t < BN / 4)
            ((float4*)sj_s)[t] = ((const float4*)(g_sj + j0))[t];
        // adj tile: 64 rows x 32 int4, into padded w buffer
#pragma unroll
        for (int k = 0; k < 8; k++) {
            const int idx = t + k * 256;
            const int r = idx >> 5;
            const int c4 = idx & 31;
            *(int4*)&wi_s[r * BNP + c4 * 4] =
                *(const int4*)&adj[(size_t)(i0 + r) * NN + j0 + c4 * 4];
        }
        __syncthreads();

        // convert adj -> w in place
#pragma unroll
        for (int k = 0; k < 8; k++) {
            const int idx = t + k * 256;
            const int r = idx >> 5;
            const int c0 = (idx & 31) << 2;
            int4 av = *(const int4*)&wi_s[r * BNP + c0];
            float4 sj4 = *(const float4*)&sj_s[c0];
            const float sir = si_s[r];
            float4 wv;
            {
                float e = sir + sj4.x; e = (e > 0.f) ? e : LEAK * e;
                wv.x = av.x ? __expf(e) : 0.f;
            }
            {
                float e = sir + sj4.y; e = (e > 0.f) ? e : LEAK * e;
                wv.y = av.y ? __expf(e) : 0.f;
            }
            {
                float e = sir + sj4.z; e = (e > 0.f) ? e : LEAK * e;
                wv.z = av.z ? __expf(e) : 0.f;
            }
            {
                float e = sir + sj4.w; e = (e > 0.f) ? e : LEAK * e;
                wv.w = av.w ? __expf(e) : 0.f;
            }
            *(float4*)&w_s[r * BNP + c0] = wv;
        }
        __syncthreads();

        // FMA phase: acc[r][f-pair] += w[r][jj] * h[jj][f-pair]
        const float* wr0 = w_s + r0 * BNP;
        const float* wr1 = w_s + r1 * BNP;
#pragma unroll 8
        for (int jj = 0; jj < BN; jj++) {
            const float w0 = wr0[jj];
            const float w1 = wr1[jj];
            const ull w0p = pack2(w0);
            const ull w1p = pack2(w1);
            const ull* hp = (const ull*)(h_s + jj * OUT_F + f0);
            ulonglong2 hA = *(const ulonglong2*)(hp);
            ulonglong2 hB = *(const ulonglong2*)(hp + 2);
            ffma2(a00, w0p, hA.x); ffma2(a01, w0p, hA.y);
            ffma2(a02, w0p, hB.x); ffma2(a03, w0p, hB.y);
            ffma2(a10, w1p, hA.x); ffma2(a11, w1p, hA.y);
            ffma2(a12, w1p, hB.x); ffma2(a13, w1p, hB.y);
            if (fg == 0) { d0 += w0; d1 += w1; }
        }
    }

    if (fg == 0) { denom_s[r0] = d0; denom_s[r1] = d1; }
    __syncthreads();

    const float inv0 = 1.0f / denom_s[r0];
    const float inv1 = 1.0f / denom_s[r1];
    const float gm0 = g_gamma[i0 + r0], bt0 = g_beta[i0 + r0];
    const float gm1 = g_gamma[i0 + r1], bt1 = g_beta[i0 + r1];

    union { ull u; float2 f; } c;
    float* o0 = out + (size_t)(i0 + r0) * OUT_F + f0;
    float* o1 = out + (size_t)(i0 + r1) * OUT_F + f0;

    float4 v;
    c.u = a00; v.x = fmaf(gm0, c.f.x * inv0, bt0); v.y = fmaf(gm0, c.f.y * inv0, bt0);
    c.u = a01; v.z = fmaf(gm0, c.f.x * inv0, bt0); v.w = fmaf(gm0, c.f.y * inv0, bt0);
    *(float4*)o0 = v;
    c.u = a02; v.x = fmaf(gm0, c.f.x * inv0, bt0); v.y = fmaf(gm0, c.f.y * inv0, bt0);
    c.u = a03; v.z = fmaf(gm0, c.f.x * inv0, bt0); v.w = fmaf(gm0, c.f.y * inv0, bt0);
    *(float4*)(o0 + 4) = v;
    c.u = a10; v.x = fmaf(gm1, c.f.x * inv1, bt1); v.y = fmaf(gm1, c.f.y * inv1, bt1);
    c.u = a11; v.z = fmaf(gm1, c.f.x * inv1, bt1); v.w = fmaf(gm1, c.f.y * inv1, bt1);
    *(float4*)o1 = v;
    c.u = a12; v.x = fmaf(gm1, c.f.x * inv1, bt1); v.y = fmaf(gm1, c.f.y * inv1, bt1);
    c.u = a13; v.z = fmaf(gm1, c.f.x * inv1, bt1); v.w = fmaf(gm1, c.f.y * inv1, bt1);
    *(float4*)(o1 + 4) = v;
}

// ============================================================================
extern "C" void kernel_launch(void* const* d_in, const int* in_sizes, int n_in,
                              void* d_out, int out_size)
{
    const float* x   = (const float*)d_in[0];
    const int*   adj = (const int*)d_in[1];
    const float* W   = (const float*)d_in[2];
    const float* a_i = (const float*)d_in[3];
    const float* a_j = (const float*)d_in[4];
    const float* w_g = (const float*)d_in[5];
    const float* w_b = (const float*)d_in[6];
    float* out = (float*)d_out;

    // idempotent; safe under graph capture (not a stream op, no allocation)
    cudaFuncSetAttribute(prep_kernel, cudaFuncAttributeMaxDynamicSharedMemorySize, PREP_SMEM);
    cudaFuncSetAttribute(attn_kernel, cudaFuncAttributeMaxDynamicSharedMemorySize, MAIN_SMEM);

    prep_kernel<<<NN / 32, 256, PREP_SMEM>>>(x, W, a_i, a_j, w_g, w_b);
    attn_kernel<<<NN / BM, 256, MAIN_SMEM>>>(adj, out);
}

// round 4
// speedup vs baseline: 2.1529x; 2.1529x over previous
#include <cuda_runtime.h>
#include <cstdint>

#define NN 8192
#define IN_F 256
#define OUT_F 64
#define LEAK 0.2f

// ---------------- scratch (device globals; no runtime allocation) ----------
__device__ float g_h[NN * OUT_F];   // tf32-rounded h, row-major [j][f]
__device__ float g_si[NN];
__device__ float g_sj[NN];
__device__ float g_gamma[NN];
__device__ float g_beta[NN];

// ---------------- helpers ---------------------------------------------------
__device__ __forceinline__ float to_tf32(float x) {
    uint32_t u;
    asm("cvt.rna.tf32.f32 %0, %1;" : "=r"(u) : "f"(x));
    return __uint_as_float(u);
}

__device__ __forceinline__ void mma_tf32(float& c0, float& c1, float& c2, float& c3,
                                         uint32_t a0, uint32_t a1, uint32_t a2, uint32_t a3,
                                         uint32_t b0, uint32_t b1)
{
    asm volatile("mma.sync.aligned.m16n8k8.row.col.f32.tf32.tf32.f32 "
                 "{%0,%1,%2,%3}, {%4,%5,%6,%7}, {%8,%9}, {%0,%1,%2,%3};"
                 : "+f"(c0), "+f"(c1), "+f"(c2), "+f"(c3)
                 : "r"(a0), "r"(a1), "r"(a2), "r"(a3), "r"(b0), "r"(b1));
}

// ============================================================================
// Kernel 1: h = x @ W ; s_i, s_j, gamma, beta (exact fp32); g_h tf32-rounded
// ============================================================================
#define PREP_SMEM ((IN_F * OUT_F + 32 * IN_F + 4 * OUT_F) * 4)

__global__ __launch_bounds__(256, 1) void prep_kernel(
    const float* __restrict__ x, const float* __restrict__ W,
    const float* __restrict__ a_i, const float* __restrict__ a_j,
    const float* __restrict__ w_g, const float* __restrict__ w_b)
{
    extern __shared__ float sm[];
    float* Ws = sm;                          // [256][64]
    float* xs = Ws + IN_F * OUT_F;           // [32][256]
    float* vs = xs + 32 * IN_F;              // 4 x [64]

    const int t = threadIdx.x;
    const int row0 = blockIdx.x * 32;

    for (int i = t; i < IN_F * OUT_F / 4; i += 256)
        ((float4*)Ws)[i] = ((const float4*)W)[i];
    for (int i = t; i < 32 * IN_F / 4; i += 256)
        ((float4*)xs)[i] = ((const float4*)(x + (size_t)row0 * IN_F))[i];
    if (t < OUT_F) {
        vs[t]             = a_i[t];
        vs[OUT_F + t]     = a_j[t];
        vs[2 * OUT_F + t] = w_g[t];
        vs[3 * OUT_F + t] = w_b[t];
    }
    __syncthreads();

    const int row = t >> 3;
    const int fg  = t & 7;
    const int f0  = fg * 8;

    float acc[8];
#pragma unroll
    for (int i = 0; i < 8; i++) acc[i] = 0.0f;

    const float* xr = xs + row * IN_F;
#pragma unroll 4
    for (int k = 0; k < IN_F; k++) {
        const float xv = xr[k];
        const float* wr = Ws + k * OUT_F + f0;
#pragma unroll
        for (int ff = 0; ff < 8; ff++) acc[ff] = fmaf(xv, wr[ff], acc[ff]);
    }

    const int grow = row0 + row;
    float4* hp = (float4*)(g_h + (size_t)grow * OUT_F + f0);
    hp[0] = make_float4(to_tf32(acc[0]), to_tf32(acc[1]), to_tf32(acc[2]), to_tf32(acc[3]));
    hp[1] = make_float4(to_tf32(acc[4]), to_tf32(acc[5]), to_tf32(acc[6]), to_tf32(acc[7]));

    float psi = 0.f, psj = 0.f, pg = 0.f, pb = 0.f;
#pragma unroll
    for (int ff = 0; ff < 8; ff++) {
        const float a = acc[ff];
        psi = fmaf(a, vs[f0 + ff], psi);
        psj = fmaf(a, vs[OUT_F + f0 + ff], psj);
        pg  = fmaf(a, vs[2 * OUT_F + f0 + ff], pg);
        pb  = fmaf(a, vs[3 * OUT_F + f0 + ff], pb);
    }
#pragma unroll
    for (int off = 4; off > 0; off >>= 1) {
        psi += __shfl_down_sync(0xffffffffu, psi, off);
        psj += __shfl_down_sync(0xffffffffu, psj, off);
        pg  += __shfl_down_sync(0xffffffffu, pg,  off);
        pb  += __shfl_down_sync(0xffffffffu, pb,  off);
    }
    if (fg == 0) {
        g_si[grow]    = psi;
        g_sj[grow]    = psj;
        g_gamma[grow] = pg + 1.0f;
        g_beta[grow]  = pb;
    }
}

// ============================================================================
// Kernel 2: fused masked softmax-attention via mma.sync tf32 + FiLM.
// 128 blocks x 256 threads (8 warps). Block = 64 rows, j-tile BN=256.
// Warp layout: K-split 8 — each warp computes the full 64x64 output for its
// 1/8 of the K-chunks (zero fragment duplication). 128 fp32 accums/thread.
// ============================================================================
#define BN 256
#define HSTR 72     // h_s stride (mod 32 == 8): conflict-free B-frag reads
#define WSTR 260    // w_s stride (mod 32 == 4): conflict-free A-frag reads
#define PSTR 68     // partial stride: conflict-free epilogue reads

#define OFF_H   0                       // h_s [256][72] -> 18432 floats
#define OFF_W   18432                   // w_s [64][260] -> 16640 floats
#define OFF_DEN 35072                   // denom [64]
#define SMEM_FLOATS 35136
#define ATTN_SMEM (SMEM_FLOATS * 4)
// epilogue partials [8][64][68] = 34816 floats, overlaid on h_s/w_s (< OFF_DEN)

__global__ __launch_bounds__(256, 1) void attn_kernel(
    const int* __restrict__ adj, float* __restrict__ out)
{
    extern __shared__ float sf[];
    const int t    = threadIdx.x;
    const int lane = t & 31;
    const int wid  = t >> 5;
    const int g    = lane >> 2;   // mma groupID
    const int tg   = lane & 3;    // mma threadID-in-group
    const int i0   = blockIdx.x * 64;

    const int r  = t >> 2;        // gen row 0..63
    const int cc = t & 3;         // gen col lane

    const float si_r = g_si[i0 + r];
    const int4*   adjp = (const int4*)(adj + (size_t)(i0 + r) * NN);
    const float4* hg4  = (const float4*)g_h;
    const float4* sj4  = (const float4*)g_sj;

    float acc[128];
#pragma unroll
    for (int i = 0; i < 128; i++) acc[i] = 0.0f;
    float dsum = 0.0f;

    for (int tile = 0; tile < NN / BN; tile++) {
        const int j0 = tile * BN;
        __syncthreads();   // previous mma phase done with smem

        // ---- phase A: copy h tile + generate w tile (gmem reads only) ----
#pragma unroll
        for (int it = 0; it < 16; it++) {
            const int i  = t + it * 256;
            const int k  = i >> 4;
            const int n4 = i & 15;
            float4 v = hg4[j0 * 16 + i];
            *(float4*)&sf[OFF_H + k * HSTR + n4 * 4] = v;
        }
#pragma unroll
        for (int q = 0; q < 16; q++) {
            const int col = cc * 4 + q * 16;
            const int gi  = (j0 >> 2) + cc + q * 4;
            const int4   a = adjp[gi];
            const float4 s = sj4[gi];
            float w0, w1, w2, w3, e;
            e = si_r + s.x; e = e > 0.f ? e : LEAK * e; w0 = a.x ? __expf(e) : 0.f;
            e = si_r + s.y; e = e > 0.f ? e : LEAK * e; w1 = a.y ? __expf(e) : 0.f;
            e = si_r + s.z; e = e > 0.f ? e : LEAK * e; w2 = a.z ? __expf(e) : 0.f;
            e = si_r + s.w; e = e > 0.f ? e : LEAK * e; w3 = a.w ? __expf(e) : 0.f;
            dsum += (w0 + w1) + (w2 + w3);
            *(float4*)&sf[OFF_W + r * WSTR + col] =
                make_float4(to_tf32(w0), to_tf32(w1), to_tf32(w2), to_tf32(w3));
        }
        __syncthreads();

        // ---- phase B: mma. warp wid handles k-chunks c8 = wid, wid+8, ... ----
        const uint32_t* wsu = (const uint32_t*)&sf[OFF_W];
        const uint32_t* hsu = (const uint32_t*)&sf[OFF_H];
        for (int c8 = wid; c8 < BN / 8; c8 += 8) {
            const int kb = c8 * 8;
            uint32_t ka[16];
#pragma unroll
            for (int mt = 0; mt < 4; mt++) {
                const uint32_t* wp = wsu + (mt * 16 + g) * WSTR + kb + tg;
                ka[mt * 4 + 0] = wp[0];
                ka[mt * 4 + 1] = wp[8 * WSTR];
                ka[mt * 4 + 2] = wp[4];
                ka[mt * 4 + 3] = wp[8 * WSTR + 4];
            }
#pragma unroll
            for (int nt = 0; nt < 8; nt++) {
                const uint32_t b0 = hsu[(kb + tg) * HSTR + nt * 8 + g];
                const uint32_t b1 = hsu[(kb + tg + 4) * HSTR + nt * 8 + g];
#pragma unroll
                for (int mt = 0; mt < 4; mt++) {
                    float* c = &acc[(mt * 8 + nt) * 4];
                    mma_tf32(c[0], c[1], c[2], c[3],
                             ka[mt * 4], ka[mt * 4 + 1], ka[mt * 4 + 2], ka[mt * 4 + 3],
                             b0, b1);
                }
            }
        }
    }

    __syncthreads();   // mma done; smem now reusable for partials

    // ---- stage K-split partials ----
    {
        float* part = sf + wid * (64 * PSTR);
#pragma unroll
        for (int mt = 0; mt < 4; mt++)
#pragma unroll
            for (int nt = 0; nt < 8; nt++) {
                const float* c = &acc[(mt * 8 + nt) * 4];
                const int m = mt * 16 + g;
                const int n = nt * 8 + tg * 2;
                *(float2*)&part[m * PSTR + n]       = make_float2(c[0], c[1]);
                *(float2*)&part[(m + 8) * PSTR + n] = make_float2(c[2], c[3]);
            }
    }
    // ---- denominator (exact fp32, accumulated during gen) ----
    dsum += __shfl_down_sync(0xffffffffu, dsum, 2);
    dsum += __shfl_down_sync(0xffffffffu, dsum, 1);
    if (cc == 0) sf[OFF_DEN + r] = dsum;
    __syncthreads();

    // ---- reduce 8 partials + FiLM + store ----
    {
        const int m  = t >> 2;
        const int n0 = (t & 3) * 16;
        const float inv = 1.0f / sf[OFF_DEN + m];
        const float gm  = g_gamma[i0 + m];
        const float bt  = g_beta[i0 + m];
        float4* o = (float4*)(out + (size_t)(i0 + m) * OUT_F + n0);
#pragma unroll
        for (int j = 0; j < 4; j++) {
            float sx = 0.f, sy = 0.f, sz = 0.f, sw = 0.f;
#pragma unroll
            for (int w = 0; w < 8; w++) {
                const float4 p = *(const float4*)&sf[w * (64 * PSTR) + m * PSTR + n0 + j * 4];
                sx += p.x; sy += p.y; sz += p.z; sw += p.w;
            }
            o[j] = make_float4(fmaf(gm, sx * inv, bt), fmaf(gm, sy * inv, bt),
                               fmaf(gm, sz * inv, bt), fmaf(gm, sw * inv, bt));
        }
    }
}

// ============================================================================
extern "C" void kernel_launch(void* const* d_in, const int* in_sizes, int n_in,
                              void* d_out, int out_size)
{
    const float* x   = (const float*)d_in[0];
    const int*   adj = (const int*)d_in[1];
    const float* W   = (const float*)d_in[2];
    const float* a_i = (const float*)d_in[3];
    const float* a_j = (const float*)d_in[4];
    const float* w_g = (const float*)d_in[5];
    const float* w_b = (const float*)d_in[6];
    float* out = (float*)d_out;

    cudaFuncSetAttribute(prep_kernel, cudaFuncAttributeMaxDynamicSharedMemorySize, PREP_SMEM);
    cudaFuncSetAttribute(attn_kernel, cudaFuncAttributeMaxDynamicSharedMemorySize, ATTN_SMEM);

    prep_kernel<<<NN / 32, 256, PREP_SMEM>>>(x, W, a_i, a_j, w_g, w_b);
    attn_kernel<<<NN / 64, 256, ATTN_SMEM>>>(adj, out);
}

// round 6
// speedup vs baseline: 4.0436x; 1.8783x over previous
#include <cuda_runtime.h>
#include <cstdint>

#define NN 8192
#define IN_F 256
#define OUT_F 64
#define LEAK 0.2f

// ---------------- scratch (device globals; no runtime allocation) ----------
__device__ float g_h[NN * OUT_F];   // tf32-rounded h, row-major [j][f]
__device__ float g_si[NN];
__device__ float g_sj[NN];
__device__ float g_gamma[NN];
__device__ float g_beta[NN];

// ---------------- helpers ---------------------------------------------------
__device__ __forceinline__ float to_tf32(float x) {
    uint32_t u;
    asm("cvt.rna.tf32.f32 %0, %1;" : "=r"(u) : "f"(x));
    return __uint_as_float(u);
}

__device__ __forceinline__ uint32_t smem_u32(const void* p) {
    uint32_t a;
    asm("{ .reg .u64 t; cvta.to.shared.u64 t, %1; cvt.u32.u64 %0, t; }"
        : "=r"(a) : "l"(p));
    return a;
}

__device__ __forceinline__ void mma_tf32(float& c0, float& c1, float& c2, float& c3,
                                         uint32_t a0, uint32_t a1, uint32_t a2, uint32_t a3,
                                         uint32_t b0, uint32_t b1)
{
    asm volatile("mma.sync.aligned.m16n8k8.row.col.f32.tf32.tf32.f32 "
                 "{%0,%1,%2,%3}, {%4,%5,%6,%7}, {%8,%9}, {%0,%1,%2,%3};"
                 : "+f"(c0), "+f"(c1), "+f"(c2), "+f"(c3)
                 : "r"(a0), "r"(a1), "r"(a2), "r"(a3), "r"(b0), "r"(b1));
}

#define CP_ASYNC16(dst, src) \
    asm volatile("cp.async.cg.shared.global [%0], [%1], 16;" :: "r"(dst), "l"(src) : "memory")
#define CP_COMMIT() asm volatile("cp.async.commit_group;" ::: "memory")
#define CP_WAIT0()  asm volatile("cp.async.wait_group 0;" ::: "memory")

// ============================================================================
// Kernel 1: h = x @ W ; s_i, s_j, gamma, beta (exact fp32); g_h tf32-rounded
// 128 blocks x 512 threads, 64 rows/block.
// ============================================================================
#define PREP_SMEM ((IN_F * OUT_F + 64 * IN_F + 4 * OUT_F) * 4)

__global__ __launch_bounds__(512, 1) void prep_kernel(
    const float* __restrict__ x, const float* __restrict__ W,
    const float* __restrict__ a_i, const float* __restrict__ a_j,
    const float* __restrict__ w_g, const float* __restrict__ w_b)
{
    extern __shared__ float sm[];
    float* Ws = sm;                          // [256][64]
    float* xs = Ws + IN_F * OUT_F;           // [64][256]
    float* vs = xs + 64 * IN_F;              // 4 x [64]

    const int t = threadIdx.x;
    const int row0 = blockIdx.x * 64;

    for (int i = t; i < IN_F * OUT_F / 4; i += 512)
        ((float4*)Ws)[i] = ((const float4*)W)[i];
    for (int i = t; i < 64 * IN_F / 4; i += 512)
        ((float4*)xs)[i] = ((const float4*)(x + (size_t)row0 * IN_F))[i];
    if (t < OUT_F) {
        vs[t]             = a_i[t];
        vs[OUT_F + t]     = a_j[t];
        vs[2 * OUT_F + t] = w_g[t];
        vs[3 * OUT_F + t] = w_b[t];
    }
    __syncthreads();

    const int row = t >> 3;        // 0..63
    const int fg  = t & 7;
    const int f0  = fg * 8;

    float acc[8];
#pragma unroll
    for (int i = 0; i < 8; i++) acc[i] = 0.0f;

    const float* xr = xs + row * IN_F;
#pragma unroll 4
    for (int k = 0; k < IN_F; k++) {
        const float xv = xr[k];
        const float* wr = Ws + k * OUT_F + f0;
#pragma unroll
        for (int ff = 0; ff < 8; ff++) acc[ff] = fmaf(xv, wr[ff], acc[ff]);
    }

    const int grow = row0 + row;
    float4* hp = (float4*)(g_h + (size_t)grow * OUT_F + f0);
    hp[0] = make_float4(to_tf32(acc[0]), to_tf32(acc[1]), to_tf32(acc[2]), to_tf32(acc[3]));
    hp[1] = make_float4(to_tf32(acc[4]), to_tf32(acc[5]), to_tf32(acc[6]), to_tf32(acc[7]));

    float psi = 0.f, psj = 0.f, pg = 0.f, pb = 0.f;
#pragma unroll
    for (int ff = 0; ff < 8; ff++) {
        const float a = acc[ff];
        psi = fmaf(a, vs[f0 + ff], psi);
        psj = fmaf(a, vs[OUT_F + f0 + ff], psj);
        pg  = fmaf(a, vs[2 * OUT_F + f0 + ff], pg);
        pb  = fmaf(a, vs[3 * OUT_F + f0 + ff], pb);
    }
#pragma unroll
    for (int off = 4; off > 0; off >>= 1) {
        psi += __shfl_down_sync(0xffffffffu, psi, off);
        psj += __shfl_down_sync(0xffffffffu, psj, off);
        pg  += __shfl_down_sync(0xffffffffu, pg,  off);
        pb  += __shfl_down_sync(0xffffffffu, pb,  off);
    }
    if (fg == 0) {
        g_si[grow]    = psi;
        g_sj[grow]    = psj;
        g_gamma[grow] = pg + 1.0f;
        g_beta[grow]  = pb;
    }
}

// ============================================================================
// Kernel 2: fused masked softmax-attention via mma.sync tf32 + FiLM.
// 128 blocks x 512 threads (16 warps). Block = 64 rows, j-tile BN=128.
// cp.async double-buffered adj+h; sj persistent in SMEM.
// Warp split: kh = wid&7 (K-eighth), mh = wid>>3 (M-half) -> 64 accums/thread.
// ============================================================================
#define BN   128
#define ASTR 132    // adj / w row stride (conflict-free with 16B chunks)
#define HSTR 72     // h_s stride: conflict-free B-frag reads
#define PSTR 68     // epilogue partial stride

#define OFF_SJ  0                        // 8192 floats
#define OFF_H   8192                     // 2 x 128 x 72 = 18432
#define OFF_ADJ 26624                    // 2 x 64 x 132 = 16896 (ints)
#define OFF_W   43520                    // 64 x 132 = 8448
#define OFF_DEN 51968                    // 64
#define SMEM_FLOATS 52032
#define ATTN_SMEM (SMEM_FLOATS * 4)      // 208128 B
// epilogue partials [8][64][68] = 34816 floats overlay at offset 0

__global__ __launch_bounds__(512, 1) void attn_kernel(
    const int* __restrict__ adj, float* __restrict__ out)
{
    extern __shared__ float sf[];
    const uint32_t sbase = smem_u32(sf);

    const int t    = threadIdx.x;
    const int lane = t & 31;
    const int wid  = t >> 5;
    const int g    = lane >> 2;   // mma groupID
    const int tg   = lane & 3;    // mma threadID-in-group
    const int i0   = blockIdx.x * 64;

    const int r  = t >> 3;        // gen row 0..63
    const int cc = t & 7;         // gen col lane 0..7

    const int kh = wid & 7;       // K-eighth
    const int mh = wid >> 3;      // M-half

    const float si_r = g_si[i0 + r];
    const char* adj_row = (const char*)(adj + (size_t)(i0 + r) * NN);

    // ---- prologue: sj preload + tile 0 (adj, h) via cp.async, one group ----
    {
        // sj: 8192 floats = 2048 x 16B
#pragma unroll
        for (int it = 0; it < 4; it++) {
            const int c = t + it * 512;
            CP_ASYNC16(sbase + (OFF_SJ + c * 4) * 4, (const char*)g_sj + c * 16);
        }
        // adj tile 0: row r, 4 chunks per thread (gi = cc + q*8, q=0..3)
        // -> covers all 32 int4 chunks of the 128-int row
#pragma unroll
        for (int q = 0; q < 4; q++) {
            const int gi = cc + q * 8;
            CP_ASYNC16(sbase + (OFF_ADJ + r * ASTR + gi * 4) * 4,
                       adj_row + gi * 16);
        }
        // h tile 0: 2048 x 16B chunks
#pragma unroll
        for (int it = 0; it < 4; it++) {
            const int c = t + it * 512;          // 0..2047
            const int k = c >> 4, n4 = c & 15;
            CP_ASYNC16(sbase + (OFF_H + k * HSTR + n4 * 4) * 4,
                       (const char*)g_h + c * 16);
        }
        CP_COMMIT();
    }

    float acc[2][8][4];
#pragma unroll
    for (int a = 0; a < 2; a++)
#pragma unroll
        for (int b = 0; b < 8; b++)
#pragma unroll
            for (int c = 0; c < 4; c++) acc[a][b][c] = 0.0f;
    float dsum = 0.0f;

    for (int tile = 0; tile < NN / BN; tile++) {
        const int buf = tile & 1;
        CP_WAIT0();
        __syncthreads();

        // ---- issue next tile's cp.async (into other buffer) ----
        if (tile + 1 < NN / BN) {
            const int nbuf = buf ^ 1;
            const int j1 = (tile + 1) * BN;
#pragma unroll
            for (int q = 0; q < 4; q++) {
                const int gi = cc + q * 8;
                CP_ASYNC16(sbase + (OFF_ADJ + nbuf * 64 * ASTR + r * ASTR + gi * 4) * 4,
                           adj_row + (size_t)j1 * 4 + gi * 16);
            }
#pragma unroll
            for (int it = 0; it < 4; it++) {
                const int c = t + it * 512;
                const int k = c >> 4, n4 = c & 15;
                CP_ASYNC16(sbase + (OFF_H + nbuf * 128 * HSTR + k * HSTR + n4 * 4) * 4,
                           (const char*)(g_h + (size_t)j1 * OUT_F) + c * 16);
            }
            CP_COMMIT();
        }

        // ---- gen: w = adj ? exp(lrelu(si + sj)) : 0  (all from SMEM) ----
        {
            const int4*   arow = (const int4*)(sf + OFF_ADJ + buf * 64 * ASTR + r * ASTR);
            const float4* sjr  = (const float4*)(sf + OFF_SJ + tile * BN);
            float4* wrow = (float4*)(sf + OFF_W + r * ASTR);
#pragma unroll
            for (int q = 0; q < 4; q++) {
                const int gi = cc + q * 8;
                const int4   a = arow[gi];
                const float4 s = sjr[gi];
                float w0, w1, w2, w3, e;
                e = si_r + s.x; e = e > 0.f ? e : LEAK * e; w0 = a.x ? __expf(e) : 0.f;
                e = si_r + s.y; e = e > 0.f ? e : LEAK * e; w1 = a.y ? __expf(e) : 0.f;
                e = si_r + s.z; e = e > 0.f ? e : LEAK * e; w2 = a.z ? __expf(e) : 0.f;
                e = si_r + s.w; e = e > 0.f ? e : LEAK * e; w3 = a.w ? __expf(e) : 0.f;
                dsum += (w0 + w1) + (w2 + w3);
                wrow[gi] = make_float4(to_tf32(w0), to_tf32(w1), to_tf32(w2), to_tf32(w3));
            }
        }
        __syncthreads();

        // ---- mma: warp (kh, mh): rows mh*32..+31, k-cols kh*16..+15 ----
        {
            const uint32_t* wsu = (const uint32_t*)(sf + OFF_W);
            const uint32_t* hsu = (const uint32_t*)(sf + OFF_H + buf * 128 * HSTR);
#pragma unroll
            for (int kc = 0; kc < 2; kc++) {
                const int k0 = kh * 16 + kc * 8;
                uint32_t ka[2][4];
#pragma unroll
                for (int mt = 0; mt < 2; mt++) {
                    const uint32_t* wp = wsu + (mh * 32 + mt * 16 + g) * ASTR + k0 + tg;
                    ka[mt][0] = wp[0];
                    ka[mt][1] = wp[8 * ASTR];
                    ka[mt][2] = wp[4];
                    ka[mt][3] = wp[8 * ASTR + 4];
                }
#pragma unroll
                for (int nt = 0; nt < 8; nt++) {
                    const uint32_t b0 = hsu[(k0 + tg) * HSTR + nt * 8 + g];
                    const uint32_t b1 = hsu[(k0 + tg + 4) * HSTR + nt * 8 + g];
#pragma unroll
                    for (int mt = 0; mt < 2; mt++) {
                        float* c = acc[mt][nt];
                        mma_tf32(c[0], c[1], c[2], c[3],
                                 ka[mt][0], ka[mt][1], ka[mt][2], ka[mt][3], b0, b1);
                    }
                }
            }
        }
    }

    __syncthreads();   // all mma done; smem reusable for partials

    // ---- stage K-split partials + denominators ----
    {
        float* part = sf + kh * (64 * PSTR);
#pragma unroll
        for (int mt = 0; mt < 2; mt++)
#pragma unroll
            for (int nt = 0; nt < 8; nt++) {
                const float* c = acc[mt][nt];
                const int m = mh * 32 + mt * 16 + g;
                const int n = nt * 8 + tg * 2;
                *(float2*)&part[m * PSTR + n]       = make_float2(c[0], c[1]);
                *(float2*)&part[(m + 8) * PSTR + n] = make_float2(c[2], c[3]);
            }
    }
    dsum += __shfl_down_sync(0xffffffffu, dsum, 4);
    dsum += __shfl_down_sync(0xffffffffu, dsum, 2);
    dsum += __shfl_down_sync(0xffffffffu, dsum, 1);
    if (cc == 0) sf[OFF_DEN + r] = dsum;
    __syncthreads();

    // ---- reduce 8 partials + FiLM + store ----
    {
        const int m  = t >> 3;
        const int n0 = (t & 7) * 8;
        const float inv = 1.0f / sf[OFF_DEN + m];
        const float gm  = g_gamma[i0 + m];
        const float bt  = g_beta[i0 + m];
        float* o = out + (size_t)(i0 + m) * OUT_F + n0;
#pragma unroll
        for (int j = 0; j < 2; j++) {
            float sx = 0.f, sy = 0.f, sz = 0.f, sw = 0.f;
#pragma unroll
            for (int w = 0; w < 8; w++) {
                const float4 p = *(const float4*)&sf[w * (64 * PSTR) + m * PSTR + n0 + j * 4];
                sx += p.x; sy += p.y; sz += p.z; sw += p.w;
            }
            *(float4*)(o + j * 4) =
                make_float4(fmaf(gm, sx * inv, bt), fmaf(gm, sy * inv, bt),
                            fmaf(gm, sz * inv, bt), fmaf(gm, sw * inv, bt));
        }
    }
}

// ============================================================================
extern "C" void kernel_launch(void* const* d_in, const int* in_sizes, int n_in,
                              void* d_out, int out_size)
{
    const float* x   = (const float*)d_in[0];
    const int*   adj = (const int*)d_in[1];
    const float* W   = (const float*)d_in[2];
    const float* a_i = (const float*)d_in[3];
    const float* a_j = (const float*)d_in[4];
    const float* w_g = (const float*)d_in[5];
    const float* w_b = (const float*)d_in[6];
    float* out = (float*)d_out;

    cudaFuncSetAttribute(prep_kernel, cudaFuncAttributeMaxDynamicSharedMemorySize, PREP_SMEM);
    cudaFuncSetAttribute(attn_kernel, cudaFuncAttributeMaxDynamicSharedMemorySize, ATTN_SMEM);

    prep_kernel<<<NN / 64, 512, PREP_SMEM>>>(x, W, a_i, a_j, w_g, w_b);
    attn_kernel<<<NN / 64, 512, ATTN_SMEM>>>(adj, out);
}